// round 5
// baseline (speedup 1.0000x reference)
#include <cuda_runtime.h>
#include <cuda_bf16.h>
#include <math.h>

#define BB 4
#define CC 32
#define PP 262144
#define NI 8
#define EE 512
#define NPTS 4096
#define NPAIRS 28

#define STATS_BLKS 1024          // BB * 256 chunks
#define SEL_BLKS 32              // BB * NI
#define K1_BLKS (SEL_BLKS + STATS_BLKS)
#define GATH_BLKS 256
#define K2_BLKS (4 + GATH_BLKS)
#define VAR_BLKS 1024
#define PAIR_BLKS (BB * NPAIRS * 32)   // 3584
#define K3_BLKS (VAR_BLKS + PAIR_BLKS) // 4608

// ---------------- device scratch (static globals; no allocations) -------------
// Accumulated via atomics in K1, consumed AND cleared by K2 -> no zero kernel.
__device__ float g_sums[BB][NI][CC];
__device__ float g_counts[BB][NI];
// Overwritten every call:
__device__ float g_means[BB][NI][CC];
__device__ float g_invc[BB][NI];
__device__ int   g_sel[BB][NI][EE];
__device__ __align__(16) __nv_bfloat16 g_ebh[BB][NPTS][CC];
__device__ float g_sq[BB][NPTS];
__device__ float g_var_part[VAR_BLKS];
__device__ float g_edge_part[PAIR_BLKS];
__device__ float g_dist_part[BB];
__device__ float g_reg_part[BB];
__device__ int   g_ticket;   // reset to 0 by the last K3 block every call

// ============================ K1: stats + select ==============================
// blocks [0,32): edge selection (b = blk>>3, inst = blk&7), 256 threads
// blocks [32,1056): label sums + counts (1024 chunks), 256 threads
#define CHPX_S 1024

__global__ __launch_bounds__(256) void k1(const float* __restrict__ feat,
                                          const int* __restrict__ labels,
                                          const int* __restrict__ labelEdges) {
    int t = threadIdx.x;
    int lane = t & 31, wid = t >> 5;

    if (blockIdx.x < SEL_BLKS) {
        // ---------------- select: first EE pixels per (b, inst) ----------------
        int b = blockIdx.x >> 3;
        int inst = blockIdx.x & 7;
        const int* le = labelEdges + (size_t)b * PP;
        const int PT = PP / 256;           // 1024 px per thread
        int start = t * PT;

        int cnt = 0;
#pragma unroll 8
        for (int k = 0; k < PT / 4; k++) {
            int4 q = *(const int4*)&le[start + k * 4];
            cnt += (q.x == inst) + (q.y == inst) + (q.z == inst) + (q.w == inst);
        }
        int v = cnt;
#pragma unroll
        for (int off = 1; off < 32; off <<= 1) {
            int u = __shfl_up_sync(0xffffffffu, v, off);
            if (lane >= off) v += u;
        }
        __shared__ int wsum[8];
        if (lane == 31) wsum[wid] = v;
        __syncthreads();
        if (wid == 0) {
            int x = (lane < 8) ? wsum[lane] : 0;
#pragma unroll
            for (int off = 1; off < 8; off <<= 1) {
                int u = __shfl_up_sync(0xffffffffu, x, off);
                if (lane >= off) x += u;
            }
            if (lane < 8) wsum[lane] = x;
        }
        __syncthreads();
        int rank = (wid ? wsum[wid - 1] : 0) + v - cnt;   // exclusive prefix
        if (rank < EE && cnt > 0) {
            for (int k = 0; k < PT / 4; k++) {
                int4 q = *(const int4*)&le[start + k * 4];
                int p = start + k * 4;
                if (q.x == inst) { if (rank < EE) g_sel[b][inst][rank] = p;     rank++; }
                if (q.y == inst) { if (rank < EE) g_sel[b][inst][rank] = p + 1; rank++; }
                if (q.z == inst) { if (rank < EE) g_sel[b][inst][rank] = p + 2; rank++; }
                if (q.w == inst) { if (rank < EE) g_sel[b][inst][rank] = p + 3; rank++; }
                if (rank >= EE) break;
            }
        }
        return;
    }

    // ------------------------- stats: sums + counts ---------------------------
    int sb = blockIdx.x - SEL_BLKS;
    int b = sb >> 8;
    int chunk = sb & 255;
    int base = chunk * CHPX_S;
    const float* f = feat + (size_t)b * CC * PP;
    const int* lb = labels + (size_t)b * PP;

    __shared__ int slab[CHPX_S];
    *(int4*)&slab[t * 4] = *(const int4*)&lb[base + t * 4];
    __syncthreads();

    int c0 = wid * 4;
    float acc[NI][4];
#pragma unroll
    for (int n = 0; n < NI; n++)
#pragma unroll
        for (int e = 0; e < 4; e++) acc[n][e] = 0.0f;

    // double-buffered channel-quad loads
    const float* fb = f + base;
    int po = lane * 4;
    float4 va = *(const float4*)&fb[(size_t)(c0 + 0) * PP + po];
    float4 vb = *(const float4*)&fb[(size_t)(c0 + 1) * PP + po];
    float4 vc = *(const float4*)&fb[(size_t)(c0 + 2) * PP + po];
    float4 vd = *(const float4*)&fb[(size_t)(c0 + 3) * PP + po];
#pragma unroll
    for (int it = 0; it < 8; it++) {
        float4 na, nb, nc, nd;
        if (it < 7) {
            int pn = (it + 1) * 128 + lane * 4;
            na = *(const float4*)&fb[(size_t)(c0 + 0) * PP + pn];
            nb = *(const float4*)&fb[(size_t)(c0 + 1) * PP + pn];
            nc = *(const float4*)&fb[(size_t)(c0 + 2) * PP + pn];
            nd = *(const float4*)&fb[(size_t)(c0 + 3) * PP + pn];
        }
        int l[4] = { slab[po], slab[po + 1], slab[po + 2], slab[po + 3] };
        float vj[4][4] = { {va.x, vb.x, vc.x, vd.x},
                           {va.y, vb.y, vc.y, vd.y},
                           {va.z, vb.z, vc.z, vd.z},
                           {va.w, vb.w, vc.w, vd.w} };
#pragma unroll
        for (int j = 0; j < 4; j++) {
#pragma unroll
            for (int n = 0; n < NI; n++) {
                float m = (l[j] == n) ? 1.0f : 0.0f;
                acc[n][0] = fmaf(m, vj[j][0], acc[n][0]);
                acc[n][1] = fmaf(m, vj[j][1], acc[n][1]);
                acc[n][2] = fmaf(m, vj[j][2], acc[n][2]);
                acc[n][3] = fmaf(m, vj[j][3], acc[n][3]);
            }
        }
        va = na; vb = nb; vc = nc; vd = nd;
        po += 128;
    }

#pragma unroll
    for (int n = 0; n < NI; n++)
#pragma unroll
        for (int e = 0; e < 4; e++) {
            float a = acc[n][e];
#pragma unroll
            for (int o = 16; o > 0; o >>= 1) a += __shfl_xor_sync(0xffffffffu, a, o);
            acc[n][e] = a;
        }
    if (lane == 0) {
#pragma unroll
        for (int n = 0; n < NI; n++)
#pragma unroll
            for (int e = 0; e < 4; e++)
                atomicAdd(&g_sums[b][n][c0 + e], acc[n][e]);
    }
    if (wid == 0) {
        int cnt[NI];
#pragma unroll
        for (int n = 0; n < NI; n++) cnt[n] = 0;
        for (int i = lane; i < CHPX_S; i += 32) {
            int l = slab[i];
#pragma unroll
            for (int n = 0; n < NI; n++) cnt[n] += (l == n);
        }
#pragma unroll
        for (int n = 0; n < NI; n++) {
            int a = cnt[n];
#pragma unroll
            for (int o = 16; o > 0; o >>= 1) a += __shfl_xor_sync(0xffffffffu, a, o);
            cnt[n] = a;
        }
        if (lane == 0) {
#pragma unroll
            for (int n = 0; n < NI; n++)
                atomicAdd(&g_counts[b][n], (float)cnt[n]);
        }
    }
}

// ======================= K2: means/dist/reg + gather ==========================
// blocks [0,4): means (+ clears g_sums/g_counts for next call)
// blocks [4,260): gather edge features -> bf16 point-major + squared norms
__global__ __launch_bounds__(256) void k2(const float* __restrict__ feat) {
    int t = threadIdx.x;
    if (blockIdx.x < 4) {
        int b = blockIdx.x;
        int n = t >> 5, c = t & 31, lane = t & 31;
        float cntv = g_counts[b][n];
        float mean = g_sums[b][n][c] / cntv;
        g_means[b][n][c] = mean;
        if (c == 0) g_invc[b][n] = 1.0f / cntv;
        // consume-then-clear: ready for next graph replay
        g_sums[b][n][c] = 0.0f;
        if (c == 0) g_counts[b][n] = 0.0f;

        __shared__ float sm[NI][CC];
        __shared__ float sM2[NI];
        __shared__ float sdist;
        sm[n][c] = mean;
        if (t == 0) sdist = 0.0f;
        float m2 = mean * mean;
#pragma unroll
        for (int o = 16; o > 0; o >>= 1) m2 += __shfl_xor_sync(0xffffffffu, m2, o);
        if (lane == 0) sM2[n] = m2;
        __syncthreads();
        if (t < NPAIRS) {
            int i = 0, rem = t;
            while (rem >= (NI - 1) - i) { rem -= (NI - 1) - i; i++; }
            int j = i + 1 + rem;
            float d2 = 0.0f;
#pragma unroll
            for (int cc2 = 0; cc2 < CC; cc2++) {
                float df = sm[i][cc2] - sm[j][cc2];
                d2 += df * df;
            }
            float dm = sqrtf(fmaxf(d2, 0.0f) + 1e-12f);
            float h = fmaxf(3.0f - dm, 0.0f);   // 2*DD - dm
            atomicAdd(&sdist, h * h);
        }
        __syncthreads();
        if (t == 0) {
            float r = 0.0f;
#pragma unroll
            for (int nn = 0; nn < NI; nn++)
                r += sqrtf(fmaxf(sM2[nn], 0.0f) + 1e-12f);
            g_reg_part[b]  = r * (1.0f / (float)NI);
            g_dist_part[b] = sdist;
        }
        return;
    }

    // ------------------------------- gather -----------------------------------
    int gidx = (blockIdx.x - 4) * 256 + t;
    int b = gidx >> 14;
    int r = gidx & 16383;
    int pt = r >> 2;
    int cg = r & 3;
    int inst = pt >> 9;
    int e = pt & (EE - 1);
    int idx = g_sel[b][inst][e];
    const float* f = feat + (size_t)b * CC * PP;

    float sq = 0.0f;
    unsigned pk[4];
#pragma unroll
    for (int k = 0; k < 4; k++) {
        float va = f[(size_t)(cg * 8 + 2 * k) * PP + idx];
        float vb = f[(size_t)(cg * 8 + 2 * k + 1) * PP + idx];
        sq += va * va + vb * vb;
        __nv_bfloat162 h = __floats2bfloat162_rn(va, vb);
        pk[k] = *reinterpret_cast<unsigned*>(&h);
    }
    *(uint4*)&g_ebh[b][pt][cg * 8] = make_uint4(pk[0], pk[1], pk[2], pk[3]);

    sq += __shfl_xor_sync(0xffffffffu, sq, 1);
    sq += __shfl_xor_sync(0xffffffffu, sq, 2);
    if (cg == 0) g_sq[b][pt] = sq;
}

// ================== K3: var + pairs + last-block finalize =====================
struct VarS  { float sm[NI * 36]; float sinv[NI]; float wred[8]; };
struct PairS { __nv_bfloat16 As[64][40]; __nv_bfloat16 Bs[128][40];
               float sqa[64]; float sqb[128]; float wred[8]; };

__global__ __launch_bounds__(256) void k3(const float* __restrict__ feat,
                                          const int* __restrict__ labels,
                                          float* __restrict__ out) {
    __shared__ __align__(16) union { VarS v; PairS p; } S;
    __shared__ int s_last;
    __shared__ float fv[8], fe[8];

    int t = threadIdx.x;
    int lane = t & 31, wid = t >> 5;

    if (blockIdx.x < VAR_BLKS) {
        // -------------------------- variance pass ----------------------------
        int b = blockIdx.x >> 8;
        int chunk = blockIdx.x & 255;
        int base = chunk * 1024;
        const float* f = feat + (size_t)b * CC * PP;
        const int* lb = labels + (size_t)b * PP;

        { int n = wid, c = lane; S.v.sm[n * 36 + c] = g_means[b][n][c]; }
        if (t < NI) S.v.sinv[t] = g_invc[b][t];
        __syncthreads();

        int p4 = base + t * 4;
        int4 L = *(const int4*)&lb[p4];
        int lv[4] = { L.x, L.y, L.z, L.w };

        float d2[4] = { 0.0f, 0.0f, 0.0f, 0.0f };
        float4 v0 = *(const float4*)&f[(size_t)0 * PP + p4];
        float4 v1 = *(const float4*)&f[(size_t)1 * PP + p4];
        float4 v2 = *(const float4*)&f[(size_t)2 * PP + p4];
        float4 v3 = *(const float4*)&f[(size_t)3 * PP + p4];
#pragma unroll
        for (int cg = 0; cg < 8; cg++) {
            float4 n0, n1, n2, n3;
            if (cg < 7) {
                n0 = *(const float4*)&f[(size_t)(cg * 4 + 4) * PP + p4];
                n1 = *(const float4*)&f[(size_t)(cg * 4 + 5) * PP + p4];
                n2 = *(const float4*)&f[(size_t)(cg * 4 + 6) * PP + p4];
                n3 = *(const float4*)&f[(size_t)(cg * 4 + 7) * PP + p4];
            }
            float vj[4][4] = { {v0.x, v1.x, v2.x, v3.x},
                               {v0.y, v1.y, v2.y, v3.y},
                               {v0.z, v1.z, v2.z, v3.z},
                               {v0.w, v1.w, v2.w, v3.w} };
#pragma unroll
            for (int j = 0; j < 4; j++) {
                float4 m = *(const float4*)&S.v.sm[lv[j] * 36 + cg * 4];
                float t0 = vj[j][0] - m.x;
                float t1 = vj[j][1] - m.y;
                float t2 = vj[j][2] - m.z;
                float t3 = vj[j][3] - m.w;
                d2[j] += t0 * t0 + t1 * t1 + t2 * t2 + t3 * t3;
            }
            v0 = n0; v1 = n1; v2 = n2; v3 = n3;
        }

        float hsum = 0.0f;
#pragma unroll
        for (int j = 0; j < 4; j++) {
            float d = sqrtf(d2[j] + 1e-12f);
            float h = fmaxf(d - 0.5f, 0.0f);          // DV = 0.5
            hsum += h * h * S.v.sinv[lv[j]];
        }
#pragma unroll
        for (int o = 16; o > 0; o >>= 1) hsum += __shfl_xor_sync(0xffffffffu, hsum, o);
        if (lane == 0) S.v.wred[wid] = hsum;
        __syncthreads();
        if (t == 0) {
            float s = 0.0f;
#pragma unroll
            for (int w2 = 0; w2 < 8; w2++) s += S.v.wred[w2];
            g_var_part[blockIdx.x] = s;
        }
    } else {
        // --------------------------- pair loss -------------------------------
        int id = blockIdx.x - VAR_BLKS;
        int b = id / 896;
        int r2 = id % 896;
        int pair = r2 >> 5;
        int tile = r2 & 31;
        int i = 0, rem = pair;
        while (rem >= (NI - 1) - i) { rem -= (NI - 1) - i; i++; }
        int j = i + 1 + rem;
        int ti = tile >> 2, tj = tile & 3;
        int i0 = i * EE + ti * 64;
        int j0 = j * EE + tj * 128;

        {
            int row = t >> 2, ch = t & 3;
            *(uint4*)&S.p.As[row][ch * 8]      = *(const uint4*)&g_ebh[b][i0 + row][ch * 8];
            *(uint4*)&S.p.Bs[row][ch * 8]      = *(const uint4*)&g_ebh[b][j0 + row][ch * 8];
            *(uint4*)&S.p.Bs[row + 64][ch * 8] = *(const uint4*)&g_ebh[b][j0 + row + 64][ch * 8];
        }
        if (t < 64) S.p.sqa[t] = g_sq[b][i0 + t];
        else if (t < 192) S.p.sqb[t - 64] = g_sq[b][j0 + (t - 64)];
        __syncthreads();

        int wi = wid >> 1, wj = wid & 1;
        int r0 = wi * 16, cb0 = wj * 64;
        int g = lane >> 2, tq = lane & 3;

        unsigned a[2][4];
#pragma unroll
        for (int ks = 0; ks < 2; ks++) {
            int kb = ks * 16 + 2 * tq;
            a[ks][0] = *(const unsigned*)&S.p.As[r0 + g][kb];
            a[ks][1] = *(const unsigned*)&S.p.As[r0 + g + 8][kb];
            a[ks][2] = *(const unsigned*)&S.p.As[r0 + g][kb + 8];
            a[ks][3] = *(const unsigned*)&S.p.As[r0 + g + 8][kb + 8];
        }
        float sa0 = S.p.sqa[r0 + g], sa1 = S.p.sqa[r0 + g + 8];
        float acc = 0.0f;

#pragma unroll
        for (int nt = 0; nt < 8; nt++) {
            int cb = cb0 + nt * 8;
            unsigned b00 = *(const unsigned*)&S.p.Bs[cb + g][2 * tq];
            unsigned b01 = *(const unsigned*)&S.p.Bs[cb + g][2 * tq + 8];
            unsigned b10 = *(const unsigned*)&S.p.Bs[cb + g][16 + 2 * tq];
            unsigned b11 = *(const unsigned*)&S.p.Bs[cb + g][16 + 2 * tq + 8];
            float d0 = 0.0f, d1 = 0.0f, d2v = 0.0f, d3 = 0.0f;
            asm volatile(
                "mma.sync.aligned.m16n8k16.row.col.f32.bf16.bf16.f32 "
                "{%0,%1,%2,%3}, {%4,%5,%6,%7}, {%8,%9}, {%0,%1,%2,%3};"
                : "+f"(d0), "+f"(d1), "+f"(d2v), "+f"(d3)
                : "r"(a[0][0]), "r"(a[0][1]), "r"(a[0][2]), "r"(a[0][3]),
                  "r"(b00), "r"(b01));
            asm volatile(
                "mma.sync.aligned.m16n8k16.row.col.f32.bf16.bf16.f32 "
                "{%0,%1,%2,%3}, {%4,%5,%6,%7}, {%8,%9}, {%0,%1,%2,%3};"
                : "+f"(d0), "+f"(d1), "+f"(d2v), "+f"(d3)
                : "r"(a[1][0]), "r"(a[1][1]), "r"(a[1][2]), "r"(a[1][3]),
                  "r"(b10), "r"(b11));

            float sb0 = S.p.sqb[cb + 2 * tq], sb1 = S.p.sqb[cb + 2 * tq + 1];
            float q00 = sa0 + sb0 - 2.0f * d0;
            float q01 = sa0 + sb1 - 2.0f * d1;
            float q10 = sa1 + sb0 - 2.0f * d2v;
            float q11 = sa1 + sb1 - 2.0f * d3;
            if (q00 < 4.0f) { float h = fmaxf(2.0f - sqrtf(fmaxf(q00, 0.0f) + 1e-12f), 0.0f); acc += h * h; }
            if (q01 < 4.0f) { float h = fmaxf(2.0f - sqrtf(fmaxf(q01, 0.0f) + 1e-12f), 0.0f); acc += h * h; }
            if (q10 < 4.0f) { float h = fmaxf(2.0f - sqrtf(fmaxf(q10, 0.0f) + 1e-12f), 0.0f); acc += h * h; }
            if (q11 < 4.0f) { float h = fmaxf(2.0f - sqrtf(fmaxf(q11, 0.0f) + 1e-12f), 0.0f); acc += h * h; }
        }

#pragma unroll
        for (int o = 16; o > 0; o >>= 1) acc += __shfl_xor_sync(0xffffffffu, acc, o);
        if (lane == 0) S.p.wred[wid] = acc;
        __syncthreads();
        if (t == 0) {
            float s = 0.0f;
#pragma unroll
            for (int w2 = 0; w2 < 8; w2++) s += S.p.wred[w2];
            g_edge_part[id] = s;
        }
    }

    // ----------------------- ticket + last-block finalize ---------------------
    __threadfence();
    if (t == 0) {
        int old = atomicAdd(&g_ticket, 1);
        s_last = (old == K3_BLKS - 1);
    }
    __syncthreads();
    if (s_last) {
        float vs = 0.0f, es = 0.0f;
#pragma unroll
        for (int k = 0; k < VAR_BLKS / 256; k++) vs += g_var_part[t + k * 256];
#pragma unroll
        for (int k = 0; k < PAIR_BLKS / 256; k++) es += g_edge_part[t + k * 256];
#pragma unroll
        for (int o = 16; o > 0; o >>= 1) {
            vs += __shfl_xor_sync(0xffffffffu, vs, o);
            es += __shfl_xor_sync(0xffffffffu, es, o);
        }
        if (lane == 0) { fv[wid] = vs; fe[wid] = es; }
        __syncthreads();
        if (t == 0) {
            float V = 0.0f, E = 0.0f;
#pragma unroll
            for (int w2 = 0; w2 < 8; w2++) { V += fv[w2]; E += fe[w2]; }
            float dist = (g_dist_part[0] + g_dist_part[1] + g_dist_part[2] + g_dist_part[3])
                         * (1.0f / 56.0f);
            float reg  = 0.001f * (g_reg_part[0] + g_reg_part[1] + g_reg_part[2] + g_reg_part[3]);
            float var  = V * (1.0f / (float)NI);
            float edge = E * (1.0f / (512.0f * 512.0f * 56.0f));
            out[0] = var + dist + edge + reg;
            out[1] = var;
            out[2] = dist;
            out[3] = edge;
            out[4] = reg;
            g_ticket = 0;   // ready for next replay
        }
    }
}

// ------------------------------------------------------------------ launcher
extern "C" void kernel_launch(void* const* d_in, const int* in_sizes, int n_in,
                              void* d_out, int out_size) {
    const float* features   = (const float*)d_in[0];
    const int*   labels     = (const int*)d_in[1];
    const int*   labelEdges = (const int*)d_in[2];
    float* out = (float*)d_out;
    (void)in_sizes; (void)n_in; (void)out_size;

    k1<<<K1_BLKS, 256>>>(features, labels, labelEdges);
    k2<<<K2_BLKS, 256>>>(features);
    k3<<<K3_BLKS, 256>>>(features, labels, out);
}

// round 6
// speedup vs baseline: 1.9216x; 1.9216x over previous
#include <cuda_runtime.h>
#include <cuda_bf16.h>
#include <math.h>

#define BB 4
#define CC 32
#define PP 262144
#define NI 8
#define EE 512
#define NPTS 4096
#define NPAIRS 28

#define NCHUNK_SEL 32                  // chunks per image for select
#define CHPX_SEL (PP / NCHUNK_SEL)     // 8192 px per chunk
#define VAR_BLKS 1024
#define PAIR_BLKS (BB * NPAIRS * 32)   // 3584

// ---------------- device scratch (static globals; no allocations) -------------
// g_sums/g_counts: accumulated by k_stats, consumed AND cleared by k_means
// (zero-initialized at module load for the first call).
__device__ float g_sums[BB][NI][CC];
__device__ float g_counts[BB][NI];
// Overwritten every call:
__device__ float g_means[BB][NI][CC];
__device__ float g_invc[BB][NI];
__device__ int   g_cnt[BB][NCHUNK_SEL][NI];
__device__ int   g_sel[BB][NI][EE];
__device__ __align__(16) __nv_bfloat16 g_ebh[BB][NPTS][CC];
__device__ float g_sq[BB][NPTS];
__device__ float g_var_part[VAR_BLKS];
__device__ float g_edge_part[PAIR_BLKS];
__device__ float g_dist_part[BB];
__device__ float g_reg_part[BB];

// ------------------------------------------------- pass A: label sums + counts
#define NCHUNK_S 256
#define CHPX_S 1024

__global__ __launch_bounds__(256) void k_stats(const float* __restrict__ feat,
                                               const int* __restrict__ labels) {
    int b = blockIdx.x >> 8;
    int chunk = blockIdx.x & 255;
    int base = chunk * CHPX_S;
    const float* f = feat + (size_t)b * CC * PP;
    const int* lb = labels + (size_t)b * PP;

    int t = threadIdx.x;
    __shared__ int slab[CHPX_S];
    *(int4*)&slab[t * 4] = *(const int4*)&lb[base + t * 4];
    __syncthreads();

    int w = t >> 5, lane = t & 31;
    int c0 = w * 4;

    float acc[NI][4];
#pragma unroll
    for (int n = 0; n < NI; n++)
#pragma unroll
        for (int e = 0; e < 4; e++) acc[n][e] = 0.0f;

#pragma unroll
    for (int it = 0; it < 8; it++) {
        int pofs = it * 128 + lane * 4;
        const float* fp = f + base + pofs;
        float4 va = *(const float4*)&fp[(size_t)(c0 + 0) * PP];
        float4 vb = *(const float4*)&fp[(size_t)(c0 + 1) * PP];
        float4 vc = *(const float4*)&fp[(size_t)(c0 + 2) * PP];
        float4 vd = *(const float4*)&fp[(size_t)(c0 + 3) * PP];
        int l[4] = { slab[pofs], slab[pofs + 1], slab[pofs + 2], slab[pofs + 3] };
        float vj[4][4] = { {va.x, vb.x, vc.x, vd.x},
                           {va.y, vb.y, vc.y, vd.y},
                           {va.z, vb.z, vc.z, vd.z},
                           {va.w, vb.w, vc.w, vd.w} };
#pragma unroll
        for (int j = 0; j < 4; j++) {
#pragma unroll
            for (int n = 0; n < NI; n++) {
                float m = (l[j] == n) ? 1.0f : 0.0f;
                acc[n][0] = fmaf(m, vj[j][0], acc[n][0]);
                acc[n][1] = fmaf(m, vj[j][1], acc[n][1]);
                acc[n][2] = fmaf(m, vj[j][2], acc[n][2]);
                acc[n][3] = fmaf(m, vj[j][3], acc[n][3]);
            }
        }
    }

#pragma unroll
    for (int n = 0; n < NI; n++)
#pragma unroll
        for (int e = 0; e < 4; e++) {
            float a = acc[n][e];
#pragma unroll
            for (int o = 16; o > 0; o >>= 1) a += __shfl_xor_sync(0xffffffffu, a, o);
            acc[n][e] = a;
        }
    if (lane == 0) {
#pragma unroll
        for (int n = 0; n < NI; n++)
#pragma unroll
            for (int e = 0; e < 4; e++)
                atomicAdd(&g_sums[b][n][c0 + e], acc[n][e]);
    }

    if (w == 0) {
        int cnt[NI];
#pragma unroll
        for (int n = 0; n < NI; n++) cnt[n] = 0;
        for (int i = lane; i < CHPX_S; i += 32) {
            int l = slab[i];
#pragma unroll
            for (int n = 0; n < NI; n++) cnt[n] += (l == n);
        }
#pragma unroll
        for (int n = 0; n < NI; n++) {
            int a = cnt[n];
#pragma unroll
            for (int o = 16; o > 0; o >>= 1) a += __shfl_xor_sync(0xffffffffu, a, o);
            cnt[n] = a;
        }
        if (lane == 0) {
#pragma unroll
            for (int n = 0; n < NI; n++)
                atomicAdd(&g_counts[b][n], (float)cnt[n]);
        }
    }
}

// ------------- means + inv counts + dist/reg losses (+ clears stats scratch)
__global__ void k_means() {
    int b = blockIdx.x;
    int t = threadIdx.x;          // 256
    int n = t >> 5, c = t & 31;
    float cntv = g_counts[b][n];
    float mean = g_sums[b][n][c] / cntv;
    g_means[b][n][c] = mean;
    if (c == 0) g_invc[b][n] = 1.0f / cntv;
    // consume-then-clear for next replay
    g_sums[b][n][c] = 0.0f;
    if (c == 0) g_counts[b][n] = 0.0f;

    __shared__ float sm[NI][CC];
    __shared__ float sM2[NI];
    __shared__ float sdist;
    sm[n][c] = mean;
    if (t == 0) sdist = 0.0f;
    float m2 = mean * mean;
#pragma unroll
    for (int o = 16; o > 0; o >>= 1) m2 += __shfl_xor_sync(0xffffffffu, m2, o);
    if (c == 0) sM2[n] = m2;
    __syncthreads();
    if (t < NPAIRS) {
        int i = 0, rem = t;
        while (rem >= (NI - 1) - i) { rem -= (NI - 1) - i; i++; }
        int j = i + 1 + rem;
        float d2 = 0.0f;
#pragma unroll
        for (int cc2 = 0; cc2 < CC; cc2++) {
            float df = sm[i][cc2] - sm[j][cc2];
            d2 += df * df;
        }
        float dm = sqrtf(fmaxf(d2, 0.0f) + 1e-12f);
        float h = fmaxf(3.0f - dm, 0.0f);   // 2*DD - dm
        atomicAdd(&sdist, h * h);
    }
    __syncthreads();
    if (t == 0) {
        float r = 0.0f;
#pragma unroll
        for (int nn = 0; nn < NI; nn++)
            r += sqrtf(fmaxf(sM2[nn], 0.0f) + 1e-12f);
        g_reg_part[b]  = r * (1.0f / (float)NI);
        g_dist_part[b] = sdist;
    }
}

// ------------------------------------------------ pass B: variance (pull) loss
__global__ __launch_bounds__(256) void k_var(const float* __restrict__ feat,
                                             const int* __restrict__ labels) {
    int b = blockIdx.x >> 8;
    int chunk = blockIdx.x & 255;
    int base = chunk * 1024;
    const float* f = feat + (size_t)b * CC * PP;
    const int* lb = labels + (size_t)b * PP;
    int t = threadIdx.x;

    __shared__ float sm[NI * 36];
    __shared__ float sinv[NI];
    __shared__ float wred[8];
    { int n = t >> 5, c = t & 31; sm[n * 36 + c] = g_means[b][n][c]; }
    if (t < NI) sinv[t] = g_invc[b][t];
    __syncthreads();

    int p4 = base + t * 4;
    int4 L = *(const int4*)&lb[p4];
    int lv[4] = { L.x, L.y, L.z, L.w };

    float d2[4] = { 0.0f, 0.0f, 0.0f, 0.0f };
#pragma unroll
    for (int cg = 0; cg < 8; cg++) {
        float4 v0 = *(const float4*)&f[(size_t)(cg * 4 + 0) * PP + p4];
        float4 v1 = *(const float4*)&f[(size_t)(cg * 4 + 1) * PP + p4];
        float4 v2 = *(const float4*)&f[(size_t)(cg * 4 + 2) * PP + p4];
        float4 v3 = *(const float4*)&f[(size_t)(cg * 4 + 3) * PP + p4];
        float vj[4][4] = { {v0.x, v1.x, v2.x, v3.x},
                           {v0.y, v1.y, v2.y, v3.y},
                           {v0.z, v1.z, v2.z, v3.z},
                           {v0.w, v1.w, v2.w, v3.w} };
#pragma unroll
        for (int j = 0; j < 4; j++) {
            float4 m = *(const float4*)&sm[lv[j] * 36 + cg * 4];
            float t0 = vj[j][0] - m.x;
            float t1 = vj[j][1] - m.y;
            float t2 = vj[j][2] - m.z;
            float t3 = vj[j][3] - m.w;
            d2[j] += t0 * t0 + t1 * t1 + t2 * t2 + t3 * t3;
        }
    }

    float hsum = 0.0f;
#pragma unroll
    for (int j = 0; j < 4; j++) {
        float d = sqrtf(d2[j] + 1e-12f);
        float h = fmaxf(d - 0.5f, 0.0f);          // DV = 0.5
        hsum += h * h * sinv[lv[j]];
    }
#pragma unroll
    for (int o = 16; o > 0; o >>= 1) hsum += __shfl_xor_sync(0xffffffffu, hsum, o);
    if ((t & 31) == 0) wred[t >> 5] = hsum;
    __syncthreads();
    if (t == 0) {
        float s = 0.0f;
#pragma unroll
        for (int w2 = 0; w2 < 8; w2++) s += wred[w2];
        g_var_part[blockIdx.x] = s;
    }
}

// ---------------- select phase 1: per-chunk instance counts ------------------
// 128 blocks (b, chunk), 256 threads, 32 contiguous px/thread (L1-resident line)
__global__ __launch_bounds__(256) void k_selcount(const int* __restrict__ labelEdges) {
    int b = blockIdx.x >> 5;
    int chunk = blockIdx.x & 31;
    const int* le = labelEdges + (size_t)b * PP + chunk * CHPX_SEL;
    int t = threadIdx.x;
    int start = t * 32;

    int cnt[NI];
#pragma unroll
    for (int n = 0; n < NI; n++) cnt[n] = 0;
#pragma unroll
    for (int k = 0; k < 8; k++) {
        int4 q = *(const int4*)&le[start + k * 4];
#pragma unroll
        for (int n = 0; n < NI; n++)
            cnt[n] += (q.x == n) + (q.y == n) + (q.z == n) + (q.w == n);
    }
    __shared__ int wtot[8][NI];
    int lane = t & 31, wid = t >> 5;
#pragma unroll
    for (int n = 0; n < NI; n++) {
        int a = cnt[n];
#pragma unroll
        for (int o = 16; o > 0; o >>= 1) a += __shfl_xor_sync(0xffffffffu, a, o);
        if (lane == 0) wtot[wid][n] = a;
    }
    __syncthreads();
    if (t < NI) {
        int s = 0;
#pragma unroll
        for (int w = 0; w < 8; w++) s += wtot[w][t];
        g_cnt[b][chunk][t] = s;
    }
}

// ---------------- select phase 2: ranked write of first EE px ----------------
// 128 blocks; blocks whose chunk-prefix is >= EE for every instance exit fast.
__global__ __launch_bounds__(256) void k_selwrite(const int* __restrict__ labelEdges) {
    int b = blockIdx.x >> 5;
    int chunk = blockIdx.x & 31;
    int t = threadIdx.x;
    int lane = t & 31, wid = t >> 5;

    __shared__ int spre[NI];
    if (t < NI) {
        int s = 0;
        for (int c = 0; c < chunk; c++) s += g_cnt[b][c][t];
        spre[t] = s;
    }
    __syncthreads();
    bool any = false;
#pragma unroll
    for (int n = 0; n < NI; n++) any |= (spre[n] < EE);
    if (!any) return;

    const int* le = labelEdges + (size_t)b * PP + chunk * CHPX_SEL;
    int start = t * 32;

    // per-thread counts over its 32 ordered px
    int cnt[NI];
#pragma unroll
    for (int n = 0; n < NI; n++) cnt[n] = 0;
#pragma unroll
    for (int k = 0; k < 8; k++) {
        int4 q = *(const int4*)&le[start + k * 4];
#pragma unroll
        for (int n = 0; n < NI; n++)
            cnt[n] += (q.x == n) + (q.y == n) + (q.z == n) + (q.w == n);
    }

    // inclusive warp scans + cross-warp prefix per instance
    __shared__ int wtot[8][NI];
    int inc[NI];
#pragma unroll
    for (int n = 0; n < NI; n++) {
        int v = cnt[n];
#pragma unroll
        for (int off = 1; off < 32; off <<= 1) {
            int u = __shfl_up_sync(0xffffffffu, v, off);
            if (lane >= off) v += u;
        }
        inc[n] = v;
        if (lane == 31) wtot[wid][n] = v;
    }
    __syncthreads();
    __shared__ int wpre[8][NI];
    if (t < 64) {
        int w2 = t >> 3, n = t & 7;
        int s = 0;
        for (int w = 0; w < w2; w++) s += wtot[w][n];
        wpre[w2][n] = s;
    }
    __syncthreads();

    int rank[NI];
#pragma unroll
    for (int n = 0; n < NI; n++)
        rank[n] = spre[n] + wpre[wid][n] + inc[n] - cnt[n];

    // ordered write pass
#pragma unroll
    for (int k = 0; k < 8; k++) {
        int4 q = *(const int4*)&le[start + k * 4];
        int p = chunk * CHPX_SEL + start + k * 4;
        int l0 = q.x, l1 = q.y, l2 = q.z, l3 = q.w;
        if (rank[l0] < EE) g_sel[b][l0][rank[l0]] = p;     rank[l0]++;
        if (rank[l1] < EE) g_sel[b][l1][rank[l1]] = p + 1; rank[l1]++;
        if (rank[l2] < EE) g_sel[b][l2][rank[l2]] = p + 2; rank[l2]++;
        if (rank[l3] < EE) g_sel[b][l3][rank[l3]] = p + 3; rank[l3]++;
    }
}

// ------------------ gather edge features -> bf16 point-major + squared norms
__global__ __launch_bounds__(256) void k_gather(const float* __restrict__ feat) {
    int gidx = blockIdx.x * 256 + threadIdx.x;
    int b = gidx >> 14;
    int r = gidx & 16383;
    int pt = r >> 2;
    int cg = r & 3;
    int inst = pt >> 9;
    int e = pt & (EE - 1);
    int idx = g_sel[b][inst][e];
    const float* f = feat + (size_t)b * CC * PP;

    float sq = 0.0f;
    unsigned pk[4];
#pragma unroll
    for (int k = 0; k < 4; k++) {
        float va = f[(size_t)(cg * 8 + 2 * k) * PP + idx];
        float vb = f[(size_t)(cg * 8 + 2 * k + 1) * PP + idx];
        sq += va * va + vb * vb;
        __nv_bfloat162 h = __floats2bfloat162_rn(va, vb);
        pk[k] = *reinterpret_cast<unsigned*>(&h);
    }
    *(uint4*)&g_ebh[b][pt][cg * 8] = make_uint4(pk[0], pk[1], pk[2], pk[3]);

    sq += __shfl_xor_sync(0xffffffffu, sq, 1);
    sq += __shfl_xor_sync(0xffffffffu, sq, 2);
    if (cg == 0) g_sq[b][pt] = sq;
}

// ----------------------- edge pair loss via bf16 mma.sync (m16n8k16)
__global__ __launch_bounds__(256) void k_pairs() {
    int b = blockIdx.y;
    int x = blockIdx.x;
    int pair = x >> 5;
    int tile = x & 31;
    int i = 0, rem = pair;
    while (rem >= (NI - 1) - i) { rem -= (NI - 1) - i; i++; }
    int j = i + 1 + rem;
    int ti = tile >> 2, tj = tile & 3;
    int i0 = i * EE + ti * 64;
    int j0 = j * EE + tj * 128;

    __shared__ __align__(16) __nv_bfloat16 As[64][40];
    __shared__ __align__(16) __nv_bfloat16 Bs[128][40];
    __shared__ float sqa[64], sqb[128];
    __shared__ float wred[8];

    int t = threadIdx.x;
    {
        int row = t >> 2, ch = t & 3;
        *(uint4*)&As[row][ch * 8]      = *(const uint4*)&g_ebh[b][i0 + row][ch * 8];
        *(uint4*)&Bs[row][ch * 8]      = *(const uint4*)&g_ebh[b][j0 + row][ch * 8];
        *(uint4*)&Bs[row + 64][ch * 8] = *(const uint4*)&g_ebh[b][j0 + row + 64][ch * 8];
    }
    if (t < 64) sqa[t] = g_sq[b][i0 + t];
    else if (t < 192) sqb[t - 64] = g_sq[b][j0 + (t - 64)];
    __syncthreads();

    int w = t >> 5, lane = t & 31;
    int wi = w >> 1, wj = w & 1;
    int r0 = wi * 16, cb0 = wj * 64;
    int g = lane >> 2, tq = lane & 3;

    unsigned a[2][4];
#pragma unroll
    for (int ks = 0; ks < 2; ks++) {
        int kb = ks * 16 + 2 * tq;
        a[ks][0] = *(const unsigned*)&As[r0 + g][kb];
        a[ks][1] = *(const unsigned*)&As[r0 + g + 8][kb];
        a[ks][2] = *(const unsigned*)&As[r0 + g][kb + 8];
        a[ks][3] = *(const unsigned*)&As[r0 + g + 8][kb + 8];
    }
    float sa0 = sqa[r0 + g], sa1 = sqa[r0 + g + 8];
    float acc = 0.0f;

#pragma unroll
    for (int nt = 0; nt < 8; nt++) {
        int cb = cb0 + nt * 8;
        unsigned b00 = *(const unsigned*)&Bs[cb + g][2 * tq];
        unsigned b01 = *(const unsigned*)&Bs[cb + g][2 * tq + 8];
        unsigned b10 = *(const unsigned*)&Bs[cb + g][16 + 2 * tq];
        unsigned b11 = *(const unsigned*)&Bs[cb + g][16 + 2 * tq + 8];
        float d0 = 0.0f, d1 = 0.0f, d2v = 0.0f, d3 = 0.0f;
        asm volatile(
            "mma.sync.aligned.m16n8k16.row.col.f32.bf16.bf16.f32 "
            "{%0,%1,%2,%3}, {%4,%5,%6,%7}, {%8,%9}, {%0,%1,%2,%3};"
            : "+f"(d0), "+f"(d1), "+f"(d2v), "+f"(d3)
            : "r"(a[0][0]), "r"(a[0][1]), "r"(a[0][2]), "r"(a[0][3]),
              "r"(b00), "r"(b01));
        asm volatile(
            "mma.sync.aligned.m16n8k16.row.col.f32.bf16.bf16.f32 "
            "{%0,%1,%2,%3}, {%4,%5,%6,%7}, {%8,%9}, {%0,%1,%2,%3};"
            : "+f"(d0), "+f"(d1), "+f"(d2v), "+f"(d3)
            : "r"(a[1][0]), "r"(a[1][1]), "r"(a[1][2]), "r"(a[1][3]),
              "r"(b10), "r"(b11));

        float sb0 = sqb[cb + 2 * tq], sb1 = sqb[cb + 2 * tq + 1];
        float q00 = sa0 + sb0 - 2.0f * d0;
        float q01 = sa0 + sb1 - 2.0f * d1;
        float q10 = sa1 + sb0 - 2.0f * d2v;
        float q11 = sa1 + sb1 - 2.0f * d3;
        if (q00 < 4.0f) { float h = fmaxf(2.0f - sqrtf(fmaxf(q00, 0.0f) + 1e-12f), 0.0f); acc += h * h; }
        if (q01 < 4.0f) { float h = fmaxf(2.0f - sqrtf(fmaxf(q01, 0.0f) + 1e-12f), 0.0f); acc += h * h; }
        if (q10 < 4.0f) { float h = fmaxf(2.0f - sqrtf(fmaxf(q10, 0.0f) + 1e-12f), 0.0f); acc += h * h; }
        if (q11 < 4.0f) { float h = fmaxf(2.0f - sqrtf(fmaxf(q11, 0.0f) + 1e-12f), 0.0f); acc += h * h; }
    }

#pragma unroll
    for (int o = 16; o > 0; o >>= 1) acc += __shfl_xor_sync(0xffffffffu, acc, o);
    if (lane == 0) wred[w] = acc;
    __syncthreads();
    if (t == 0) {
        float s = 0.0f;
#pragma unroll
        for (int w2 = 0; w2 < 8; w2++) s += wred[w2];
        g_edge_part[blockIdx.y * (NPAIRS * 32) + blockIdx.x] = s;
    }
}

// --------------------------------------------------------------- finalize
__global__ __launch_bounds__(256) void k_final(float* __restrict__ out) {
    int t = threadIdx.x;
    int lane = t & 31, wid = t >> 5;
    __shared__ float fv[8], fe[8];
    float vs = 0.0f, es = 0.0f;
#pragma unroll
    for (int k = 0; k < VAR_BLKS / 256; k++) vs += g_var_part[t + k * 256];
#pragma unroll
    for (int k = 0; k < PAIR_BLKS / 256; k++) es += g_edge_part[t + k * 256];
#pragma unroll
    for (int o = 16; o > 0; o >>= 1) {
        vs += __shfl_xor_sync(0xffffffffu, vs, o);
        es += __shfl_xor_sync(0xffffffffu, es, o);
    }
    if (lane == 0) { fv[wid] = vs; fe[wid] = es; }
    __syncthreads();
    if (t == 0) {
        float V = 0.0f, E = 0.0f;
#pragma unroll
        for (int w2 = 0; w2 < 8; w2++) { V += fv[w2]; E += fe[w2]; }
        float dist = (g_dist_part[0] + g_dist_part[1] + g_dist_part[2] + g_dist_part[3])
                     * (1.0f / 56.0f);
        float reg  = 0.001f * (g_reg_part[0] + g_reg_part[1] + g_reg_part[2] + g_reg_part[3]);
        float var  = V * (1.0f / (float)NI);
        float edge = E * (1.0f / (512.0f * 512.0f * 56.0f));
        out[0] = var + dist + edge + reg;
        out[1] = var;
        out[2] = dist;
        out[3] = edge;
        out[4] = reg;
    }
}

// ------------------------------------------------------------------ launcher
extern "C" void kernel_launch(void* const* d_in, const int* in_sizes, int n_in,
                              void* d_out, int out_size) {
    const float* features   = (const float*)d_in[0];
    const int*   labels     = (const int*)d_in[1];
    const int*   labelEdges = (const int*)d_in[2];
    float* out = (float*)d_out;
    (void)in_sizes; (void)n_in; (void)out_size;

    k_selcount<<<BB * NCHUNK_SEL, 256>>>(labelEdges);
    k_selwrite<<<BB * NCHUNK_SEL, 256>>>(labelEdges);
    k_stats<<<BB * NCHUNK_S, 256>>>(features, labels);
    k_means<<<BB, 256>>>();
    k_gather<<<256, 256>>>(features);
    k_var<<<BB * 256, 256>>>(features, labels);
    k_pairs<<<dim3(NPAIRS * 32, BB), 256>>>();
    k_final<<<1, 256>>>(out);
}